// round 8
// baseline (speedup 1.0000x reference)
#include <cuda_runtime.h>
#include <math.h>

// Problem: GAT layer. N=4096, F_IN=128, F_OUT=64, H=4.
// Inputs: 0 nodes[4096,128] 1 degree[4096,4096] 2 dist(unused) 3 bond[4096,4096]
//         4 proj_param[4,128,64] 5 score_src[4,64,1] 6 score_tgt[4,64,1]
//         7 skip_w[256,128] 8 cutoff (scalar)
// Output: concat( out[4096,256], mask_ln[4096,4096] ) fp32.

#define NEG_INF -1e9f

// ---- scratch (device globals; no allocation allowed) ----
__device__ float g_mask[16777216];   // [4096][4096]
__device__ float g_proj[1048576];    // [h][n][o] = [4][4096][64]
__device__ float g_skip[1048576];    // [n][256]
__device__ float g_ss[16384];        // [h][n]
__device__ float g_st[16384];        // [h][n]
__device__ float g_pm[131072];       // [h][8 stripes][4096] partial col max
__device__ float g_pz[131072];       // partial col sum
__device__ float g_m[16384];         // [h][j] col max
__device__ float g_iz[16384];        // [h][j] 1/Z

// ---- packed f32x2 helpers ----
__device__ __forceinline__ unsigned long long pk2(float x, float y) {
    unsigned long long r;
    asm("mov.b64 %0, {%1,%2};" : "=l"(r) : "f"(x), "f"(y));
    return r;
}
__device__ __forceinline__ void upk2(unsigned long long v, float& x, float& y) {
    asm("mov.b64 {%0,%1}, %2;" : "=f"(x), "=f"(y) : "l"(v));
}
__device__ __forceinline__ unsigned long long fma2_(unsigned long long a,
                                                    unsigned long long b,
                                                    unsigned long long c) {
    unsigned long long d;
    asm("fma.rn.f32x2 %0, %1, %2, %3;" : "=l"(d) : "l"(a), "l"(b), "l"(c));
    return d;
}

// ---- block reduce (sum), broadcasts result to all threads ----
__device__ __forceinline__ float bred256(float v, float* red, int tid) {
    red[tid] = v;
    __syncthreads();
#pragma unroll
    for (int s = 128; s > 0; s >>= 1) {
        if (tid < s) red[tid] += red[tid + s];
        __syncthreads();
    }
    float r = red[0];
    __syncthreads();
    return r;
}

// =====================================================================
// K1: per-head projection, scalar scores, skip projection.
// grid 4096 (node), 256 threads.
// =====================================================================
__global__ void __launch_bounds__(256) k_proj(
    const float* __restrict__ nodes, const float* __restrict__ pp,
    const float* __restrict__ scs, const float* __restrict__ sct,
    const float* __restrict__ skw) {
    __shared__ float x_s[128];
    __shared__ float red[256];
    int n = blockIdx.x, tid = threadIdx.x;
    if (tid < 128) x_s[tid] = nodes[n * 128 + tid];
    __syncthreads();

    int h = tid >> 6, o = tid & 63;
    float a = 0.f;
#pragma unroll
    for (int f = 0; f < 128; f++) a = fmaf(x_s[f], pp[(h * 128 + f) * 64 + o], a);
    g_proj[(h * 4096 + n) * 64 + o] = a;

    // s_src
    red[tid] = a * scs[h * 64 + o];
    __syncthreads();
#pragma unroll
    for (int s = 32; s > 0; s >>= 1) {
        if (o < s) red[tid] += red[tid + s];
        __syncthreads();
    }
    if (o == 0) g_ss[h * 4096 + n] = red[tid];
    __syncthreads();
    // s_tgt
    red[tid] = a * sct[h * 64 + o];
    __syncthreads();
#pragma unroll
    for (int s = 32; s > 0; s >>= 1) {
        if (o < s) red[tid] += red[tid + s];
        __syncthreads();
    }
    if (o == 0) g_st[h * 4096 + n] = red[tid];

    // skip: c = tid
    float sk = 0.f;
#pragma unroll
    for (int f = 0; f < 128; f++) sk = fmaf(x_s[f], skw[tid * 128 + f], sk);
    g_skip[n * 256 + tid] = sk;
}

// =====================================================================
// K2: mask build + per-row LayerNorm (two-pass, matches jnp.var).
// grid 4096 (row), 256 threads, 16 elems/thread.
// =====================================================================
__global__ void __launch_bounds__(256) k_mask(
    const float* __restrict__ deg, const float* __restrict__ bond,
    const int* __restrict__ cutp, float* __restrict__ out_ln) {
    __shared__ float red[256];
    int i = blockIdx.x, tid = threadIdx.x;
    float cut = (float)cutp[0];
    float mv[16];
    float ssum = 0.f;
#pragma unroll
    for (int k = 0; k < 16; k++) {
        int j = tid + k * 256;
        unsigned idx = (unsigned)i * 4096u + (unsigned)j;
        float d = deg[idx], b = bond[idx];
        float wdm = d + b;
        float m = (wdm > 0.f) ? wdm : ((b > cut) ? (b + wdm) : NEG_INF);
        mv[k] = m;
        g_mask[idx] = m;
        ssum += m;
    }
    float mu = bred256(ssum, red, tid) * (1.f / 4096.f);
    float s2 = 0.f;
#pragma unroll
    for (int k = 0; k < 16; k++) {
        float d = mv[k] - mu;
        s2 = fmaf(d, d, s2);
    }
    float var = bred256(s2, red, tid) * (1.f / 4096.f);
    float rstd = rsqrtf(var + 1e-5f);
#pragma unroll
    for (int k = 0; k < 16; k++) {
        int j = tid + k * 256;
        out_ln[(unsigned)i * 4096u + (unsigned)j] = (mv[k] - mu) * rstd;
    }
}

// =====================================================================
// K3: partial column softmax stats (online max/sum over a 512-row stripe).
// grid (32 col-chunks of 128, 8 row-stripes, 4 heads), 128 threads (1 col each).
// =====================================================================
__global__ void __launch_bounds__(128) k_stats() {
    __shared__ float ss_s[512];
    int tid = threadIdx.x;
    int jc = blockIdx.x, istr = blockIdx.y, h = blockIdx.z;
    int j = jc * 128 + tid;
    int i0 = istr * 512;
#pragma unroll
    for (int k = 0; k < 4; k++) ss_s[tid + k * 128] = g_ss[h * 4096 + i0 + tid + k * 128];
    __syncthreads();
    float stj = g_st[h * 4096 + j];
    float m = -INFINITY, z = 0.f;
#pragma unroll 4
    for (int ii = 0; ii < 512; ii++) {
        float e = ss_s[ii] + stj;
        e = fmaxf(e, 0.2f * e);  // leaky_relu(0.2)
        e += g_mask[(unsigned)(i0 + ii) * 4096u + (unsigned)j];
        if (e > m) {
            z = z * __expf(m - e) + 1.f;
            m = e;
        } else {
            z += __expf(e - m);
        }
    }
    g_pm[(h * 8 + istr) * 4096 + j] = m;
    g_pz[(h * 8 + istr) * 4096 + j] = z;
}

// =====================================================================
// K4: combine the 8 stripe partials per (h,j). grid 64, 256 threads.
// =====================================================================
__global__ void __launch_bounds__(256) k_comb() {
    int idx = blockIdx.x * 256 + threadIdx.x;  // 0..16383
    int h = idx >> 12, j = idx & 4095;
    float m = -INFINITY;
#pragma unroll
    for (int s = 0; s < 8; s++) m = fmaxf(m, g_pm[(h * 8 + s) * 4096 + j]);
    float z = 0.f;
#pragma unroll
    for (int s = 0; s < 8; s++)
        z += g_pz[(h * 8 + s) * 4096 + j] * __expf(g_pm[(h * 8 + s) * 4096 + j] - m);
    g_m[h * 4096 + j] = m;
    g_iz[h * 4096 + j] = 1.0f / z;
}

// =====================================================================
// K5: aggregation out[h,i,f] = sum_j w(h,i,j)*proj[h,j,f], fused skip+ELU.
// grid (64 i-blocks of 64 rows, 4 heads), 256 threads.
// Thread tile: 2 rows x 8 f-cols, fp32x2-packed accumulators.
// Reads g_mask DIRECTLY as a device symbol (NOT via a host-passed pointer:
// the host-side shadow of a __device__ global is ATS-dereferenceable on
// GB300 and silently reads zeros — that was the R6 bug).
// =====================================================================
__global__ void __launch_bounds__(256) k_agg(float* __restrict__ out) {
    __shared__ float w_s[64][33];     // [i][j], padded: conflict-free both ways
    __shared__ float proj_s[32][64];  // [j][f]
    __shared__ float ss_s[64];
    __shared__ float st_s[32], m_s[32], iz_s[32];

    int tid = threadIdx.x;
    int ib = blockIdx.x, h = blockIdx.y;
    int i0 = ib * 64;
    if (tid < 64) ss_s[tid] = g_ss[h * 4096 + i0 + tid];

    int i_g = tid >> 3;  // 0..31
    int f_g = tid & 7;   // 0..7
    int ia = i_g * 2;
    int fb = f_g * 8;
    int jw = tid & 31;   // w-phase column
    int iw0 = tid >> 5;  // w-phase row base (warp id)

    unsigned long long acc[2][4];
#pragma unroll
    for (int a = 0; a < 2; a++)
#pragma unroll
        for (int q = 0; q < 4; q++) acc[a][q] = 0ull;

    const float* __restrict__ projg = g_proj + (h * 4096) * 64;

    for (int j0 = 0; j0 < 4096; j0 += 32) {
        __syncthreads();  // previous FMA phase done with w_s/proj_s
        if (tid < 32) {
            st_s[tid] = g_st[h * 4096 + j0 + tid];
            m_s[tid] = g_m[h * 4096 + j0 + tid];
            iz_s[tid] = g_iz[h * 4096 + j0 + tid];
        }
        float pv[8];
#pragma unroll
        for (int p = 0; p < 8; p++) {
            int idx = p * 256 + tid;
            pv[p] = projg[(j0 + (idx >> 6)) * 64 + (idx & 63)];
        }
        float mk[8];
#pragma unroll
        for (int p = 0; p < 8; p++) {
            int il = p * 8 + iw0;
            mk[p] = g_mask[(unsigned)(i0 + il) * 4096u + (unsigned)(j0 + jw)];
        }
#pragma unroll
        for (int p = 0; p < 8; p++) {
            int idx = p * 256 + tid;
            proj_s[idx >> 6][idx & 63] = pv[p];
        }
        __syncthreads();  // st/m/iz + proj_s visible
#pragma unroll
        for (int p = 0; p < 8; p++) {
            int il = p * 8 + iw0;
            float e = ss_s[il] + st_s[jw];
            e = fmaxf(e, 0.2f * e);
            e += mk[p];
            w_s[il][jw] = __expf(e - m_s[jw]) * iz_s[jw];
        }
        __syncthreads();  // w_s ready

#pragma unroll 2
        for (int jl = 0; jl < 32; jl++) {
            float wa = w_s[ia][jl];
            float wb = w_s[ia + 1][jl];
            unsigned long long w0 = pk2(wa, wa);
            unsigned long long w1 = pk2(wb, wb);
            ulonglong2 pA = *(const ulonglong2*)&proj_s[jl][fb];
            ulonglong2 pB = *(const ulonglong2*)&proj_s[jl][fb + 4];
            acc[0][0] = fma2_(w0, pA.x, acc[0][0]);
            acc[0][1] = fma2_(w0, pA.y, acc[0][1]);
            acc[0][2] = fma2_(w0, pB.x, acc[0][2]);
            acc[0][3] = fma2_(w0, pB.y, acc[0][3]);
            acc[1][0] = fma2_(w1, pA.x, acc[1][0]);
            acc[1][1] = fma2_(w1, pA.y, acc[1][1]);
            acc[1][2] = fma2_(w1, pB.x, acc[1][2]);
            acc[1][3] = fma2_(w1, pB.y, acc[1][3]);
        }
    }

    // epilogue: + skip, ELU, write [n][h*64+f]
#pragma unroll
    for (int a = 0; a < 2; a++) {
        int n = i0 + ia + a;
#pragma unroll
        for (int q = 0; q < 4; q++) {
            float x0, x1;
            upk2(acc[a][q], x0, x1);
            int c = h * 64 + fb + q * 2;
            float v0 = x0 + g_skip[n * 256 + c];
            float v1 = x1 + g_skip[n * 256 + c + 1];
            out[n * 256 + c] = (v0 > 0.f) ? v0 : expm1f(v0);
            out[n * 256 + c + 1] = (v1 > 0.f) ? v1 : expm1f(v1);
        }
    }
}

// =====================================================================
extern "C" void kernel_launch(void* const* d_in, const int* in_sizes, int n_in,
                              void* d_out, int out_size) {
    const float* nodes = (const float*)d_in[0];
    const float* deg = (const float*)d_in[1];
    // d_in[2] = edges_features_distance: unused by the reference
    const float* bond = (const float*)d_in[3];
    const float* pp = (const float*)d_in[4];
    const float* scs = (const float*)d_in[5];
    const float* sct = (const float*)d_in[6];
    const float* skw = (const float*)d_in[7];
    const int* cutp = (const int*)d_in[8];

    float* out0 = (float*)d_out;            // [4096,256]
    float* out_ln = out0 + 4096 * 256;      // [4096,4096]

    k_proj<<<4096, 256>>>(nodes, pp, scs, sct, skw);
    k_mask<<<4096, 256>>>(deg, bond, cutp, out_ln);
    k_stats<<<dim3(32, 8, 4), 128>>>();
    k_comb<<<64, 256>>>();
    k_agg<<<dim3(64, 4), 256>>>(out0);
}

// round 9
// speedup vs baseline: 2.2374x; 2.2374x over previous
#include <cuda_runtime.h>
#include <math.h>

// GAT layer. N=4096, F_IN=128, F_OUT=64, H=4.
// Inputs: 0 nodes[4096,128] 1 degree[4096,4096] 2 dist(unused) 3 bond[4096,4096]
//         4 proj_param[4,128,64] 5 score_src[4,64,1] 6 score_tgt[4,64,1]
//         7 skip_w[256,128] 8 cutoff (scalar)
// Output: concat( out[4096,256], mask_ln[4096,4096] ) fp32.

#define NEG_INF -1e9f

// ---- scratch (device globals; no allocation allowed) ----
__device__ float g_mask[16777216];   // [4096][4096]
__device__ float g_proj[1048576];    // [h][n][o] = [4][4096][64]
__device__ float g_skip[1048576];    // [n][256]
__device__ float g_ss[16384];        // [h][n]
__device__ float g_st[16384];        // [h][n]
__device__ float g_pm[131072];       // [h][8 stripes][4096] partial col max
__device__ float g_pz[131072];       // partial col sum
__device__ float g_m[16384];         // [h][j] col max
__device__ float g_iz[16384];        // [h][j] 1/Z

// ---- packed f32x2 helpers ----
__device__ __forceinline__ unsigned long long pk2(float x, float y) {
    unsigned long long r;
    asm("mov.b64 %0, {%1,%2};" : "=l"(r) : "f"(x), "f"(y));
    return r;
}
__device__ __forceinline__ void upk2(unsigned long long v, float& x, float& y) {
    asm("mov.b64 {%0,%1}, %2;" : "=f"(x), "=f"(y) : "l"(v));
}
__device__ __forceinline__ unsigned long long fma2_(unsigned long long a,
                                                    unsigned long long b,
                                                    unsigned long long c) {
    unsigned long long d;
    asm("fma.rn.f32x2 %0, %1, %2, %3;" : "=l"(d) : "l"(a), "l"(b), "l"(c));
    return d;
}

__device__ __forceinline__ float bred256(float v, float* red, int tid) {
    red[tid] = v;
    __syncthreads();
#pragma unroll
    for (int s = 128; s > 0; s >>= 1) {
        if (tid < s) red[tid] += red[tid + s];
        __syncthreads();
    }
    float r = red[0];
    __syncthreads();
    return r;
}

// =====================================================================
// K1: per-head projection + scalar scores. grid 4096, 256 threads.
// (skip projection moved to k_skip — the old skw[tid*128+f] pattern was
//  32 wavefronts per LDG and dominated the whole run.)
// =====================================================================
__global__ void __launch_bounds__(256) k_proj(
    const float* __restrict__ nodes, const float* __restrict__ pp,
    const float* __restrict__ scs, const float* __restrict__ sct) {
    __shared__ float x_s[128];
    __shared__ float red[256];
    int n = blockIdx.x, tid = threadIdx.x;
    if (tid < 128) x_s[tid] = nodes[n * 128 + tid];
    __syncthreads();

    int h = tid >> 6, o = tid & 63;
    float a = 0.f;
#pragma unroll
    for (int f = 0; f < 128; f++) a = fmaf(x_s[f], pp[(h * 128 + f) * 64 + o], a);
    g_proj[(h * 4096 + n) * 64 + o] = a;

    red[tid] = a * scs[h * 64 + o];
    __syncthreads();
#pragma unroll
    for (int s = 32; s > 0; s >>= 1) {
        if (o < s) red[tid] += red[tid + s];
        __syncthreads();
    }
    if (o == 0) g_ss[h * 4096 + n] = red[tid];
    __syncthreads();
    red[tid] = a * sct[h * 64 + o];
    __syncthreads();
#pragma unroll
    for (int s = 32; s > 0; s >>= 1) {
        if (o < s) red[tid] += red[tid + s];
        __syncthreads();
    }
    if (o == 0) g_st[h * 4096 + n] = red[tid];
}

// =====================================================================
// K1b: skip GEMM g_skip = nodes @ skw^T. grid (64,4), 256 threads.
// Tile 64 nodes x 64 cols; both operands staged coalesced into smem.
// =====================================================================
__global__ void __launch_bounds__(256) k_skip(
    const float* __restrict__ nodes, const float* __restrict__ skw) {
    __shared__ float x_s[64][129];
    __shared__ float w_s[64][129];
    int tid = threadIdx.x;
    int n0 = blockIdx.x * 64, c0 = blockIdx.y * 64;
#pragma unroll
    for (int it = 0; it < 32; it++) {
        int idx = it * 256 + tid;     // 8192 elems
        int r = idx >> 7, f = idx & 127;
        x_s[r][f] = nodes[(n0 + r) * 128 + f];
        w_s[r][f] = skw[(c0 + r) * 128 + f];
    }
    __syncthreads();
    int ti = tid >> 4, tc = tid & 15;   // 16x16 thread grid, 4x4 outputs each
    float acc[4][4];
#pragma unroll
    for (int i = 0; i < 4; i++)
#pragma unroll
        for (int j = 0; j < 4; j++) acc[i][j] = 0.f;
#pragma unroll 4
    for (int k = 0; k < 128; k++) {
        float a0 = x_s[ti * 4 + 0][k], a1 = x_s[ti * 4 + 1][k];
        float a2 = x_s[ti * 4 + 2][k], a3 = x_s[ti * 4 + 3][k];
        float b0 = w_s[tc * 4 + 0][k], b1 = w_s[tc * 4 + 1][k];
        float b2 = w_s[tc * 4 + 2][k], b3 = w_s[tc * 4 + 3][k];
        acc[0][0] = fmaf(a0, b0, acc[0][0]); acc[0][1] = fmaf(a0, b1, acc[0][1]);
        acc[0][2] = fmaf(a0, b2, acc[0][2]); acc[0][3] = fmaf(a0, b3, acc[0][3]);
        acc[1][0] = fmaf(a1, b0, acc[1][0]); acc[1][1] = fmaf(a1, b1, acc[1][1]);
        acc[1][2] = fmaf(a1, b2, acc[1][2]); acc[1][3] = fmaf(a1, b3, acc[1][3]);
        acc[2][0] = fmaf(a2, b0, acc[2][0]); acc[2][1] = fmaf(a2, b1, acc[2][1]);
        acc[2][2] = fmaf(a2, b2, acc[2][2]); acc[2][3] = fmaf(a2, b3, acc[2][3]);
        acc[3][0] = fmaf(a3, b0, acc[3][0]); acc[3][1] = fmaf(a3, b1, acc[3][1]);
        acc[3][2] = fmaf(a3, b2, acc[3][2]); acc[3][3] = fmaf(a3, b3, acc[3][3]);
    }
#pragma unroll
    for (int i = 0; i < 4; i++)
#pragma unroll
        for (int j = 0; j < 4; j++)
            g_skip[(n0 + ti * 4 + i) * 256 + c0 + tc * 4 + j] = acc[i][j];
}

// =====================================================================
// K2: mask build + per-row LayerNorm. grid 4096, 256 threads.
// =====================================================================
__global__ void __launch_bounds__(256) k_mask(
    const float* __restrict__ deg, const float* __restrict__ bond,
    const int* __restrict__ cutp, float* __restrict__ out_ln) {
    __shared__ float red[256];
    int i = blockIdx.x, tid = threadIdx.x;
    float cut = (float)cutp[0];
    float mv[16];
    float ssum = 0.f;
#pragma unroll
    for (int k = 0; k < 16; k++) {
        int j = tid + k * 256;
        unsigned idx = (unsigned)i * 4096u + (unsigned)j;
        float d = deg[idx], b = bond[idx];
        float wdm = d + b;
        float m = (wdm > 0.f) ? wdm : ((b > cut) ? (b + wdm) : NEG_INF);
        mv[k] = m;
        g_mask[idx] = m;
        ssum += m;
    }
    float mu = bred256(ssum, red, tid) * (1.f / 4096.f);
    float s2 = 0.f;
#pragma unroll
    for (int k = 0; k < 16; k++) {
        float d = mv[k] - mu;
        s2 = fmaf(d, d, s2);
    }
    float var = bred256(s2, red, tid) * (1.f / 4096.f);
    float rstd = rsqrtf(var + 1e-5f);
#pragma unroll
    for (int k = 0; k < 16; k++) {
        int j = tid + k * 256;
        out_ln[(unsigned)i * 4096u + (unsigned)j] = (mv[k] - mu) * rstd;
    }
}

// =====================================================================
// K3: partial column softmax stats. grid (32,8,4), 128 threads.
// =====================================================================
__global__ void __launch_bounds__(128) k_stats() {
    __shared__ float ss_s[512];
    int tid = threadIdx.x;
    int jc = blockIdx.x, istr = blockIdx.y, h = blockIdx.z;
    int j = jc * 128 + tid;
    int i0 = istr * 512;
#pragma unroll
    for (int k = 0; k < 4; k++) ss_s[tid + k * 128] = g_ss[h * 4096 + i0 + tid + k * 128];
    __syncthreads();
    float stj = g_st[h * 4096 + j];
    float m = -INFINITY, z = 0.f;
#pragma unroll 4
    for (int ii = 0; ii < 512; ii++) {
        float e = ss_s[ii] + stj;
        e = fmaxf(e, 0.2f * e);
        e += g_mask[(unsigned)(i0 + ii) * 4096u + (unsigned)j];
        float mn = fmaxf(m, e);               // branchless online update
        z = z * __expf(m - mn) + __expf(e - mn);
        m = mn;
    }
    g_pm[(h * 8 + istr) * 4096 + j] = m;
    g_pz[(h * 8 + istr) * 4096 + j] = z;
}

// =====================================================================
// K4: combine stripe partials. grid 64, 256 threads.
// =====================================================================
__global__ void __launch_bounds__(256) k_comb() {
    int idx = blockIdx.x * 256 + threadIdx.x;
    int h = idx >> 12, j = idx & 4095;
    float m = -INFINITY;
#pragma unroll
    for (int s = 0; s < 8; s++) m = fmaxf(m, g_pm[(h * 8 + s) * 4096 + j]);
    float z = 0.f;
#pragma unroll
    for (int s = 0; s < 8; s++)
        z += g_pz[(h * 8 + s) * 4096 + j] * __expf(g_pm[(h * 8 + s) * 4096 + j] - m);
    g_m[h * 4096 + j] = m;
    g_iz[h * 4096 + j] = 1.0f / z;
}

// =====================================================================
// K5: aggregation + skip + ELU. grid (32 i-blocks of 128, 4 heads), 256 thr.
// Thread tile 8 rows x 8 f (split-4 groups), j split across two 128-thread
// halves (16 j each per 32-j tile), pair-reduced at the end.
// =====================================================================
__global__ void __launch_bounds__(256) k_agg(float* __restrict__ out) {
    __shared__ __align__(16) float w_s[128][33];    // [i][j]
    __shared__ __align__(16) float proj_s[32][68];  // [j][f]
    __shared__ float ss_s[128];
    __shared__ float st_s[32], m_s[32], iz_s[32];

    int tid = threadIdx.x;
    int h = blockIdx.y;
    int i0 = blockIdx.x * 128;
    if (tid < 128) ss_s[tid] = g_ss[h * 4096 + i0 + tid];

    int jhalf = tid >> 7;        // 0/1: which 16-j half this thread sums
    int ct = tid & 127;
    int i_g = ct >> 3;           // 0..15 : rows {i_g*4..+3} and {64+i_g*4..+3}
    int f_g = ct & 7;            // 0..7  : cols {f_g*4..+3} and {32+f_g*4..+3}
    int jw = tid & 31;           // w-phase column lane
    int iw = tid >> 5;           // w-phase row offset (0..7)
    int jlo = jhalf * 16;

    unsigned long long acc[8][4];
#pragma unroll
    for (int r = 0; r < 8; r++)
#pragma unroll
        for (int q = 0; q < 4; q++) acc[r][q] = 0ull;

    const float* __restrict__ projg = g_proj + (h * 4096) * 64;

    for (int j0 = 0; j0 < 4096; j0 += 32) {
        __syncthreads();  // previous tile's FMA done with w_s/proj_s
        if (tid < 32) {
            st_s[tid] = g_st[h * 4096 + j0 + tid];
            m_s[tid] = g_m[h * 4096 + j0 + tid];
            iz_s[tid] = g_iz[h * 4096 + j0 + tid];
        }
        float pv[8];
#pragma unroll
        for (int p = 0; p < 8; p++) {
            int idx = p * 256 + tid;  // 2048 = 32j x 64f
            pv[p] = projg[(j0 + (idx >> 6)) * 64 + (idx & 63)];
        }
        float mk[16];
#pragma unroll
        for (int p = 0; p < 16; p++) {
            int il = p * 8 + iw;
            mk[p] = g_mask[(unsigned)(i0 + il) * 4096u + (unsigned)(j0 + jw)];
        }
#pragma unroll
        for (int p = 0; p < 8; p++) {
            int idx = p * 256 + tid;
            proj_s[idx >> 6][idx & 63] = pv[p];
        }
        __syncthreads();  // st/m/iz + proj_s visible
#pragma unroll
        for (int p = 0; p < 16; p++) {
            int il = p * 8 + iw;
            float e = ss_s[il] + st_s[jw];
            e = fmaxf(e, 0.2f * e);
            e += mk[p];
            w_s[il][jw] = __expf(e - m_s[jw]) * iz_s[jw];
        }
        __syncthreads();  // w_s ready

#pragma unroll
        for (int jj = 0; jj < 16; jj++) {
            int jl = jlo + jj;
            ulonglong2 pA = *(const ulonglong2*)&proj_s[jl][f_g * 4];
            ulonglong2 pB = *(const ulonglong2*)&proj_s[jl][32 + f_g * 4];
            float w0 = w_s[i_g * 4 + 0][jl];
            float w1 = w_s[i_g * 4 + 1][jl];
            float w2 = w_s[i_g * 4 + 2][jl];
            float w3 = w_s[i_g * 4 + 3][jl];
            float w4 = w_s[64 + i_g * 4 + 0][jl];
            float w5 = w_s[64 + i_g * 4 + 1][jl];
            float w6 = w_s[64 + i_g * 4 + 2][jl];
            float w7 = w_s[64 + i_g * 4 + 3][jl];
            unsigned long long u0 = pk2(w0, w0), u1 = pk2(w1, w1);
            unsigned long long u2 = pk2(w2, w2), u3 = pk2(w3, w3);
            unsigned long long u4 = pk2(w4, w4), u5 = pk2(w5, w5);
            unsigned long long u6 = pk2(w6, w6), u7 = pk2(w7, w7);
            acc[0][0] = fma2_(u0, pA.x, acc[0][0]); acc[0][1] = fma2_(u0, pA.y, acc[0][1]);
            acc[0][2] = fma2_(u0, pB.x, acc[0][2]); acc[0][3] = fma2_(u0, pB.y, acc[0][3]);
            acc[1][0] = fma2_(u1, pA.x, acc[1][0]); acc[1][1] = fma2_(u1, pA.y, acc[1][1]);
            acc[1][2] = fma2_(u1, pB.x, acc[1][2]); acc[1][3] = fma2_(u1, pB.y, acc[1][3]);
            acc[2][0] = fma2_(u2, pA.x, acc[2][0]); acc[2][1] = fma2_(u2, pA.y, acc[2][1]);
            acc[2][2] = fma2_(u2, pB.x, acc[2][2]); acc[2][3] = fma2_(u2, pB.y, acc[2][3]);
            acc[3][0] = fma2_(u3, pA.x, acc[3][0]); acc[3][1] = fma2_(u3, pA.y, acc[3][1]);
            acc[3][2] = fma2_(u3, pB.x, acc[3][2]); acc[3][3] = fma2_(u3, pB.y, acc[3][3]);
            acc[4][0] = fma2_(u4, pA.x, acc[4][0]); acc[4][1] = fma2_(u4, pA.y, acc[4][1]);
            acc[4][2] = fma2_(u4, pB.x, acc[4][2]); acc[4][3] = fma2_(u4, pB.y, acc[4][3]);
            acc[5][0] = fma2_(u5, pA.x, acc[5][0]); acc[5][1] = fma2_(u5, pA.y, acc[5][1]);
            acc[5][2] = fma2_(u5, pB.x, acc[5][2]); acc[5][3] = fma2_(u5, pB.y, acc[5][3]);
            acc[6][0] = fma2_(u6, pA.x, acc[6][0]); acc[6][1] = fma2_(u6, pA.y, acc[6][1]);
            acc[6][2] = fma2_(u6, pB.x, acc[6][2]); acc[6][3] = fma2_(u6, pB.y, acc[6][3]);
            acc[7][0] = fma2_(u7, pA.x, acc[7][0]); acc[7][1] = fma2_(u7, pA.y, acc[7][1]);
            acc[7][2] = fma2_(u7, pB.x, acc[7][2]); acc[7][3] = fma2_(u7, pB.y, acc[7][3]);
        }
    }

    // pair-reduce the two j-halves through smem (reuses w_s region), then
    // skip + ELU epilogue.
    __syncthreads();
    unsigned long long* red = reinterpret_cast<unsigned long long*>(&w_s[0][0]);

    // phase 0: rows 0..3 (i = i0 + i_g*4 + r), jhalf1 -> red, jhalf0 combines
    if (jhalf == 1) {
#pragma unroll
        for (int r = 0; r < 4; r++)
#pragma unroll
            for (int q = 0; q < 4; q++) red[ct * 16 + r * 4 + q] = acc[r][q];
    }
    __syncthreads();
    if (jhalf == 0) {
#pragma unroll
        for (int r = 0; r < 4; r++) {
            int n = i0 + i_g * 4 + r;
#pragma unroll
            for (int q = 0; q < 4; q++) {
                float x0, x1, y0, y1;
                upk2(acc[r][q], x0, x1);
                upk2(red[ct * 16 + r * 4 + q], y0, y1);
                x0 += y0; x1 += y1;
                int cb = (q < 2) ? (f_g * 4 + q * 2) : (32 + f_g * 4 + (q - 2) * 2);
                int c = h * 64 + cb;
                float v0 = x0 + g_skip[n * 256 + c];
                float v1 = x1 + g_skip[n * 256 + c + 1];
                out[n * 256 + c] = (v0 > 0.f) ? v0 : expm1f(v0);
                out[n * 256 + c + 1] = (v1 > 0.f) ? v1 : expm1f(v1);
            }
        }
    }
    __syncthreads();
    // phase 1: rows 4..7 (i = i0 + 64 + i_g*4 + r), jhalf0 -> red, jhalf1 combines
    if (jhalf == 0) {
#pragma unroll
        for (int r = 0; r < 4; r++)
#pragma unroll
            for (int q = 0; q < 4; q++) red[ct * 16 + r * 4 + q] = acc[4 + r][q];
    }
    __syncthreads();
    if (jhalf == 1) {
#pragma unroll
        for (int r = 0; r < 4; r++) {
            int n = i0 + 64 + i_g * 4 + r;
#pragma unroll
            for (int q = 0; q < 4; q++) {
                float x0, x1, y0, y1;
                upk2(acc[4 + r][q], x0, x1);
                upk2(red[ct * 16 + r * 4 + q], y0, y1);
                x0 += y0; x1 += y1;
                int cb = (q < 2) ? (f_g * 4 + q * 2) : (32 + f_g * 4 + (q - 2) * 2);
                int c = h * 64 + cb;
                float v0 = x0 + g_skip[n * 256 + c];
                float v1 = x1 + g_skip[n * 256 + c + 1];
                out[n * 256 + c] = (v0 > 0.f) ? v0 : expm1f(v0);
                out[n * 256 + c + 1] = (v1 > 0.f) ? v1 : expm1f(v1);
            }
        }
    }
}

// =====================================================================
extern "C" void kernel_launch(void* const* d_in, const int* in_sizes, int n_in,
                              void* d_out, int out_size) {
    const float* nodes = (const float*)d_in[0];
    const float* deg = (const float*)d_in[1];
    const float* bond = (const float*)d_in[3];
    const float* pp = (const float*)d_in[4];
    const float* scs = (const float*)d_in[5];
    const float* sct = (const float*)d_in[6];
    const float* skw = (const float*)d_in[7];
    const int* cutp = (const int*)d_in[8];

    float* out0 = (float*)d_out;        // [4096,256]
    float* out_ln = out0 + 4096 * 256;  // [4096,4096]

    k_proj<<<4096, 256>>>(nodes, pp, scs, sct);
    k_skip<<<dim3(64, 4), 256>>>(nodes, skw);
    k_mask<<<4096, 256>>>(deg, bond, cutp, out_ln);
    k_stats<<<dim3(32, 8, 4), 128>>>();
    k_comb<<<64, 256>>>();
    k_agg<<<dim3(32, 4), 256>>>(out0);
}